// round 7
// baseline (speedup 1.0000x reference)
#include <cuda_runtime.h>
#include <math.h>

#define BATCH 2
#define SEQ   2048
#define EMB   1024
#define NH    16
#define HD    64
#define QKV3  3072   // 3 * NH * HD
#define MROWS (BATCH * SEQ)   // 4096

// Scratch (allocation-free: __device__ globals)
__device__ float g_qkv[(size_t)BATCH * SEQ * QKV3];  // [b, s, {q,k,v}, h, d]
__device__ float g_att[(size_t)BATCH * SEQ * EMB];   // [b*s, h*d]

// ---------------------------------------------------------------------------
// tf32 helpers
// ---------------------------------------------------------------------------
__device__ __forceinline__ unsigned f2tf(float x) {
    unsigned u;
    asm("cvt.rna.tf32.f32 %0, %1;" : "=r"(u) : "f"(x));
    return u;
}

// D += A*B, m16n8k8, A row-major, B col-major, tf32 in / f32 accum.
__device__ __forceinline__ void mma8(float* c, const unsigned* a, const unsigned* b) {
    asm volatile(
        "mma.sync.aligned.m16n8k8.row.col.f32.tf32.tf32.f32 "
        "{%0,%1,%2,%3}, {%4,%5,%6,%7}, {%8,%9}, {%0,%1,%2,%3};"
        : "+f"(c[0]), "+f"(c[1]), "+f"(c[2]), "+f"(c[3])
        : "r"(a[0]), "r"(a[1]), "r"(a[2]), "r"(a[3]), "r"(b[0]), "r"(b[1]));
}

// ---------------------------------------------------------------------------
// tf32 tensor-core GEMM: C[M,N] = A[M,K] @ B[K,N], fp32 in/out.
// BM=128, BN=128, BK=32; 256 threads = 8 warps (4m x 2n), warp tile 32x64.
// ROPE=1: apply rotary embedding to cols < 2*EMB in the epilogue (QKV GEMM).
// ---------------------------------------------------------------------------
#define GPA 36
#define GPB 136
template <int ROPE>
__global__ __launch_bounds__(256, 2) void gemm_tf32(
    const float* __restrict__ A, const float* __restrict__ B,
    float* __restrict__ C, int M, int N, int K)
{
    __shared__ unsigned As[128][GPA];
    __shared__ unsigned Bs[32][GPB];

    const int tid  = threadIdx.x;
    const int lane = tid & 31;
    const int warp = tid >> 5;
    const int g    = lane >> 2;
    const int tg   = lane & 3;
    const int wm   = warp >> 1;
    const int wn   = warp & 1;
    const int bm   = blockIdx.y * 128;
    const int bn   = blockIdx.x * 128;

    float acc[2][8][4];
    #pragma unroll
    for (int mf = 0; mf < 2; mf++)
        #pragma unroll
        for (int nf = 0; nf < 8; nf++)
            #pragma unroll
            for (int i = 0; i < 4; i++) acc[mf][nf][i] = 0.0f;

    for (int k0 = 0; k0 < K; k0 += 32) {
        #pragma unroll
        for (int t = 0; t < 4; t++) {
            int ch = tid + t * 256;
            int ar = ch >> 3, ac = (ch & 7) * 4;
            float4 av = *(const float4*)(A + (size_t)(bm + ar) * K + k0 + ac);
            *(uint4*)&As[ar][ac] =
                make_uint4(f2tf(av.x), f2tf(av.y), f2tf(av.z), f2tf(av.w));
            int br = ch >> 5, bc = (ch & 31) * 4;
            float4 bv = *(const float4*)(B + (size_t)(k0 + br) * N + bn + bc);
            *(uint4*)&Bs[br][bc] =
                make_uint4(f2tf(bv.x), f2tf(bv.y), f2tf(bv.z), f2tf(bv.w));
        }
        __syncthreads();

        #pragma unroll
        for (int ks = 0; ks < 4; ks++) {
            unsigned a[2][4];
            #pragma unroll
            for (int mf = 0; mf < 2; mf++) {
                int r = wm * 32 + mf * 16;
                a[mf][0] = As[r + g    ][ks * 8 + tg];
                a[mf][1] = As[r + g + 8][ks * 8 + tg];
                a[mf][2] = As[r + g    ][ks * 8 + tg + 4];
                a[mf][3] = As[r + g + 8][ks * 8 + tg + 4];
            }
            #pragma unroll
            for (int nf = 0; nf < 8; nf++) {
                unsigned bb[2];
                int c = wn * 64 + nf * 8 + g;
                bb[0] = Bs[ks * 8 + tg    ][c];
                bb[1] = Bs[ks * 8 + tg + 4][c];
                mma8(acc[0][nf], a[0], bb);
                mma8(acc[1][nf], a[1], bb);
            }
        }
        __syncthreads();
    }

    #pragma unroll
    for (int mf = 0; mf < 2; mf++)
        #pragma unroll
        for (int nf = 0; nf < 8; nf++) {
            int row = bm + wm * 32 + mf * 16 + g;
            int col = bn + wn * 64 + nf * 8 + 2 * tg;
            float c0 = acc[mf][nf][0], c1 = acc[mf][nf][1];
            float c2 = acc[mf][nf][2], c3 = acc[mf][nf][3];
            if (ROPE && col < 2 * EMB) {
                int d = col & 63;  // even
                float freq = exp2f((float)d * -0.2076205059304601f); // 10000^(-d/64)
                int s0 = row & (SEQ - 1);
                int s1 = (row + 8) & (SEQ - 1);
                float sn0, cs0, sn1, cs1;
                sincosf((float)s0 * freq, &sn0, &cs0);
                sincosf((float)s1 * freq, &sn1, &cs1);
                float n0 = c0 * cs0 - c1 * sn0, n1 = c0 * sn0 + c1 * cs0;
                float n2 = c2 * cs1 - c3 * sn1, n3 = c2 * sn1 + c3 * cs1;
                c0 = n0; c1 = n1; c2 = n2; c3 = n3;
            }
            *(float2*)(C + (size_t)row * N + col)       = make_float2(c0, c1);
            *(float2*)(C + (size_t)(row + 8) * N + col) = make_float2(c2, c3);
        }
}

// ---------------------------------------------------------------------------
// Flash attention, tf32 mma, pipelined.
// Block: 256 threads (8 warps), 128 q-rows; kv tile 64, double-buffered K/V.
// Warp w owns q-rows w*16..w*16+15. One __syncthreads per kv-tile.
// Smem (dynamic, words of u32):
//   Qp [128][72]  pair-packed tf32 Q (scaled by 1/8), rows natural.
//   Kp [2][64][72] pair-packed tf32 K, rows = kv natural.
//   Vs [2][64][72] tf32 V, rows sigma-permuted so S-accum layout == PV A-frag.
// Pair packing within an 8-col group: orig d = 8a+u -> col 8a + 2*(u&3) + (u>>2)
// so B-frag pair {d=k*8+tg, d=k*8+tg+4} is one aligned uint2.
// V row perm: gmem kv row 8a+u stored at row 8a + ((u&1) ? (u>>1)+4 : (u>>1)),
// matching A-frag k-slots fed with pa = {s0, s2, s1, s3} from the S accumulator.
// ---------------------------------------------------------------------------
#define SM_QOFF 0
#define SM_KOFF 9216
#define SM_VOFF 18432
#define SSTRIDE 72
#define ATTN_SMEM_BYTES (27648 * 4)

__global__ __launch_bounds__(256, 2) void attn_mma(
    const float* __restrict__ qkv, float* __restrict__ out)
{
    extern __shared__ unsigned sm[];
    const int tid  = threadIdx.x;
    const int lane = tid & 31;
    const int warp = tid >> 5;
    const int g    = lane >> 2;
    const int tg   = lane & 3;
    const int qt   = gridDim.x - 1 - blockIdx.x;  // heavy blocks first
    const int h    = blockIdx.y;
    const int b    = blockIdx.z;
    const int q0   = qt * 128;
    const int m0   = warp * 16;

    const float* qb = qkv + (size_t)b * SEQ * QKV3 + h * HD;
    const float* kb = qb + EMB;
    const float* vb = qb + 2 * EMB;

    // ---- Q prologue: 128x64, pair-packed, scaled by 1/8 ----
    #pragma unroll
    for (int t = 0; t < 8; t++) {
        int idx = tid + t * 256;
        int r = idx >> 4, c4 = (idx & 15) * 4;
        float4 v = *(const float4*)(qb + (size_t)(q0 + r) * QKV3 + c4);
        float vv[4] = {v.x, v.y, v.z, v.w};
        #pragma unroll
        for (int j = 0; j < 4; j++) {
            int d = c4 + j;
            int col = (d & ~7) + 2 * (d & 3) + ((d >> 2) & 1);
            sm[SM_QOFF + r * SSTRIDE + col] = f2tf(0.125f * vv[j]);
        }
    }

    const int last = 2 * qt + 1;
    float4 kpf[4], vpf[4];

    // ---- initial K/V tile 0 load + store to buf 0 ----
    #pragma unroll
    for (int t = 0; t < 4; t++) {
        int idx = tid + t * 256;
        int r = idx >> 4, c4 = (idx & 15) * 4;
        kpf[t] = *(const float4*)(kb + (size_t)r * QKV3 + c4);
        vpf[t] = *(const float4*)(vb + (size_t)r * QKV3 + c4);
    }
    #pragma unroll
    for (int t = 0; t < 4; t++) {
        int idx = tid + t * 256;
        int r = idx >> 4, c4 = (idx & 15) * 4;
        float kk[4] = {kpf[t].x, kpf[t].y, kpf[t].z, kpf[t].w};
        #pragma unroll
        for (int j = 0; j < 4; j++) {
            int d = c4 + j;
            int col = (d & ~7) + 2 * (d & 3) + ((d >> 2) & 1);
            sm[SM_KOFF + r * SSTRIDE + col] = f2tf(kk[j]);
        }
        int u = r & 7, a = r >> 3;
        int rp = 8 * a + ((u & 1) ? (u >> 1) + 4 : (u >> 1));
        *(uint4*)(sm + SM_VOFF + rp * SSTRIDE + c4) =
            make_uint4(f2tf(vpf[t].x), f2tf(vpf[t].y), f2tf(vpf[t].z), f2tf(vpf[t].w));
    }

    float m_r[2] = {-1e30f, -1e30f};
    float l_r[2] = {0.0f, 0.0f};
    float o[8][4];
    #pragma unroll
    for (int nf = 0; nf < 8; nf++)
        #pragma unroll
        for (int i = 0; i < 4; i++) o[nf][i] = 0.0f;

    for (int kt = 0; kt <= last; kt++) {
        __syncthreads();
        const int cur = kt & 1;
        const int k0  = kt * 64;
        const bool have_next = (kt < last);

        // prefetch next K/V tile into registers
        if (have_next) {
            int kn = k0 + 64;
            #pragma unroll
            for (int t = 0; t < 4; t++) {
                int idx = tid + t * 256;
                int r = idx >> 4, c4 = (idx & 15) * 4;
                kpf[t] = *(const float4*)(kb + (size_t)(kn + r) * QKV3 + c4);
                vpf[t] = *(const float4*)(vb + (size_t)(kn + r) * QKV3 + c4);
            }
        }

        const bool active = (k0 <= q0 + m0 + 15);
        float s[8][4];

        if (active) {
            #pragma unroll
            for (int nf = 0; nf < 8; nf++)
                #pragma unroll
                for (int i = 0; i < 4; i++) s[nf][i] = 0.0f;

            const unsigned* Kc = sm + SM_KOFF + cur * 4608;
            #pragma unroll
            for (int ks = 0; ks < 8; ks++) {
                uint2 qa0 = *(const uint2*)(sm + SM_QOFF + (m0 + g)     * SSTRIDE + ks * 8 + 2 * tg);
                uint2 qa1 = *(const uint2*)(sm + SM_QOFF + (m0 + g + 8) * SSTRIDE + ks * 8 + 2 * tg);
                unsigned a[4] = {qa0.x, qa1.x, qa0.y, qa1.y};
                #pragma unroll
                for (int nf = 0; nf < 8; nf++) {
                    uint2 kv2 = *(const uint2*)(Kc + (nf * 8 + g) * SSTRIDE + ks * 8 + 2 * tg);
                    unsigned bbv[2] = {kv2.x, kv2.y};
                    mma8(s[nf], a, bbv);
                }
            }
        }

        // store prefetched tile (LDG latency covered by S phase)
        if (have_next) {
            const int nb = cur ^ 1;
            unsigned* Kd = sm + SM_KOFF + nb * 4608;
            unsigned* Vd = sm + SM_VOFF + nb * 4608;
            #pragma unroll
            for (int t = 0; t < 4; t++) {
                int idx = tid + t * 256;
                int r = idx >> 4, c4 = (idx & 15) * 4;
                float kk[4] = {kpf[t].x, kpf[t].y, kpf[t].z, kpf[t].w};
                #pragma unroll
                for (int j = 0; j < 4; j++) {
                    int d = c4 + j;
                    int col = (d & ~7) + 2 * (d & 3) + ((d >> 2) & 1);
                    Kd[r * SSTRIDE + col] = f2tf(kk[j]);
                }
                int u = r & 7, a = r >> 3;
                int rp = 8 * a + ((u & 1) ? (u >> 1) + 4 : (u >> 1));
                *(uint4*)(Vd + rp * SSTRIDE + c4) =
                    make_uint4(f2tf(vpf[t].x), f2tf(vpf[t].y), f2tf(vpf[t].z), f2tf(vpf[t].w));
            }
        }

        if (active) {
            // causal mask (only tiles overlapping the diagonal of this warp)
            if (k0 + 63 > q0 + m0) {
                int r0 = q0 + m0 + g, r1 = r0 + 8;
                #pragma unroll
                for (int nf = 0; nf < 8; nf++) {
                    int col = k0 + nf * 8 + 2 * tg;
                    if (col     > r0) s[nf][0] = -1e9f;
                    if (col + 1 > r0) s[nf][1] = -1e9f;
                    if (col     > r1) s[nf][2] = -1e9f;
                    if (col + 1 > r1) s[nf][3] = -1e9f;
                }
            }

            // online softmax (row i=0 -> g, i=1 -> g+8; reduce over 4 tg lanes)
            #pragma unroll
            for (int i = 0; i < 2; i++) {
                float mx = -1e30f;
                #pragma unroll
                for (int nf = 0; nf < 8; nf++)
                    mx = fmaxf(mx, fmaxf(s[nf][2 * i], s[nf][2 * i + 1]));
                mx = fmaxf(mx, __shfl_xor_sync(0xffffffffu, mx, 1));
                mx = fmaxf(mx, __shfl_xor_sync(0xffffffffu, mx, 2));
                float mn   = fmaxf(m_r[i], mx);
                float corr = __expf(m_r[i] - mn);
                m_r[i] = mn;
                float rs = 0.0f;
                #pragma unroll
                for (int nf = 0; nf < 8; nf++) {
                    float p0 = __expf(s[nf][2 * i]     - mn);
                    float p1 = __expf(s[nf][2 * i + 1] - mn);
                    s[nf][2 * i] = p0; s[nf][2 * i + 1] = p1;
                    rs += p0 + p1;
                }
                rs += __shfl_xor_sync(0xffffffffu, rs, 1);
                rs += __shfl_xor_sync(0xffffffffu, rs, 2);
                l_r[i] = l_r[i] * corr + rs;
                #pragma unroll
                for (int nf = 0; nf < 8; nf++) {
                    o[nf][2 * i]     *= corr;
                    o[nf][2 * i + 1] *= corr;
                }
            }

            // O += P @ V  (P stays in registers; V rows sigma-permuted)
            const unsigned* Vc = sm + SM_VOFF + cur * 4608;
            #pragma unroll
            for (int ks = 0; ks < 8; ks++) {
                unsigned pa[4] = {f2tf(s[ks][0]), f2tf(s[ks][2]),
                                  f2tf(s[ks][1]), f2tf(s[ks][3])};
                #pragma unroll
                for (int nf = 0; nf < 8; nf++) {
                    unsigned bbv[2];
                    bbv[0] = Vc[(ks * 8 + tg)     * SSTRIDE + nf * 8 + g];
                    bbv[1] = Vc[(ks * 8 + tg + 4) * SSTRIDE + nf * 8 + g];
                    mma8(o[nf], pa, bbv);
                }
            }
        }
    }

    // ---- epilogue: normalize, store [b*s, h*d] ----
    #pragma unroll
    for (int i = 0; i < 2; i++) {
        float inv = 1.0f / l_r[i];
        int row = q0 + m0 + g + 8 * i;
        float* op = out + ((size_t)b * SEQ + row) * EMB + h * HD;
        #pragma unroll
        for (int nf = 0; nf < 8; nf++) {
            int col = nf * 8 + 2 * tg;
            *(float2*)(op + col) =
                make_float2(o[nf][2 * i] * inv, o[nf][2 * i + 1] * inv);
        }
    }
}

// ---------------------------------------------------------------------------
extern "C" void kernel_launch(void* const* d_in, const int* in_sizes, int n_in,
                              void* d_out, int out_size)
{
    const float* x    = (const float*)d_in[0];   // [2,2048,1024]
    const float* Wqkv = (const float*)d_in[1];   // [1024,3072]
    const float* Wout = (const float*)d_in[2];   // [1024,1024]
    float* out        = (float*)d_out;           // [2,2048,1024]

    float* qkv = nullptr;
    float* att = nullptr;
    cudaGetSymbolAddress((void**)&qkv, g_qkv);
    cudaGetSymbolAddress((void**)&att, g_att);

    static bool attr_set = false;
    if (!attr_set) {
        cudaFuncSetAttribute(attn_mma,
            cudaFuncAttributeMaxDynamicSharedMemorySize, ATTN_SMEM_BYTES);
        attr_set = true;
    }

    // 1) QKV projection + fused RoPE: [4096,1024] @ [1024,3072]
    {
        dim3 grid(QKV3 / 128, MROWS / 128);
        gemm_tf32<1><<<grid, 256>>>(x, Wqkv, qkv, MROWS, QKV3, EMB);
    }
    // 2) Causal flash attention (tf32 mma, pipelined)
    {
        dim3 grid(SEQ / 128, NH, BATCH);
        attn_mma<<<grid, 256, ATTN_SMEM_BYTES>>>(qkv, att);
    }
    // 3) Output projection: [4096,1024] @ [1024,1024]
    {
        dim3 grid(EMB / 128, MROWS / 128);
        gemm_tf32<0><<<grid, 256>>>(att, Wout, out, MROWS, EMB, EMB);
    }
}

// round 8
// speedup vs baseline: 1.2267x; 1.2267x over previous
#include <cuda_runtime.h>
#include <math.h>

#define BATCH 2
#define SEQ   2048
#define EMB   1024
#define NH    16
#define HD    64
#define QKV3  3072   // 3 * NH * HD
#define MROWS (BATCH * SEQ)   // 4096

// Scratch (allocation-free: __device__ globals)
__device__ float    g_qkv[(size_t)MROWS * QKV3];  // tf32 bit patterns after QKV gemm
__device__ float    g_att[(size_t)MROWS * EMB];   // tf32 bit patterns after attn
__device__ unsigned g_xt [(size_t)MROWS * EMB];   // x  converted to tf32 bits
__device__ unsigned g_wqt[(size_t)EMB * QKV3];    // W_qkv tf32 bits
__device__ unsigned g_wot[(size_t)EMB * EMB];     // W_out tf32 bits

// ---------------------------------------------------------------------------
__device__ __forceinline__ unsigned f2tf(float x) {
    unsigned u;
    asm("cvt.rna.tf32.f32 %0, %1;" : "=r"(u) : "f"(x));
    return u;
}

// D += A*B, m16n8k8, A row-major, B col-major, tf32 in / f32 accum.
__device__ __forceinline__ void mma8(float* c, const unsigned* a, const unsigned* b) {
    asm volatile(
        "mma.sync.aligned.m16n8k8.row.col.f32.tf32.tf32.f32 "
        "{%0,%1,%2,%3}, {%4,%5,%6,%7}, {%8,%9}, {%0,%1,%2,%3};"
        : "+f"(c[0]), "+f"(c[1]), "+f"(c[2]), "+f"(c[3])
        : "r"(a[0]), "r"(a[1]), "r"(a[2]), "r"(a[3]), "r"(b[0]), "r"(b[1]));
}

__device__ __forceinline__ void cp16(unsigned* smem_dst, const void* gptr) {
    unsigned sa = (unsigned)__cvta_generic_to_shared(smem_dst);
    asm volatile("cp.async.cg.shared.global [%0], [%1], 16;" :: "r"(sa), "l"(gptr));
}

// ---------------------------------------------------------------------------
// Pre-pass: fp32 -> tf32 bit patterns, vectorized.
// ---------------------------------------------------------------------------
__global__ __launch_bounds__(256) void cvt_tf32_kernel(
    const float4* __restrict__ src, uint4* __restrict__ dst, int n4)
{
    int i = blockIdx.x * 256 + threadIdx.x;
    if (i < n4) {
        float4 v = src[i];
        dst[i] = make_uint4(f2tf(v.x), f2tf(v.y), f2tf(v.z), f2tf(v.w));
    }
}

// ---------------------------------------------------------------------------
// tf32 tensor-core GEMM, cp.async double-buffered.
// C[M,N] = A[M,K] @ B[K,N]; A,B are tf32 bit patterns. BM=BN=128, BK=32,
// 256 threads = 8 warps (4m x 2n), warp tile 32x64.
// ROPE=1: rotary on cols < 2*EMB in epilogue, store tf32 bits (QKV gemm).
// ROPE=0: plain fp32 store (output projection).
// Smem: As[2][128][36], Bs[2][32][136] (conflict-free pads), 71680 B dynamic.
// ---------------------------------------------------------------------------
#define AS_STG  4608   // 128*36 words per stage
#define BS_STG  4352   // 32*136 words per stage
#define BS_BASE 9216   // 2*AS_STG
#define GEMM_SMEM_BYTES ((2 * AS_STG + 2 * BS_STG) * 4)

template <int ROPE>
__global__ __launch_bounds__(256, 2) void gemm_tc(
    const unsigned* __restrict__ A, const unsigned* __restrict__ B,
    float* __restrict__ C, int M, int N, int K)
{
    extern __shared__ unsigned sm[];

    const int tid  = threadIdx.x;
    const int lane = tid & 31;
    const int warp = tid >> 5;
    const int g    = lane >> 2;
    const int tg   = lane & 3;
    const int wm   = warp >> 1;
    const int wn   = warp & 1;
    const int bm   = blockIdx.y * 128;
    const int bn   = blockIdx.x * 128;
    const int nt   = K >> 5;

    auto issue = [&](int kt, int s) {
        const int k0 = kt * 32;
        #pragma unroll
        for (int t = 0; t < 4; t++) {
            int ch = tid + t * 256;
            int ar = ch >> 3, ac = (ch & 7) * 4;
            cp16(sm + s * AS_STG + ar * 36 + ac,
                 A + (size_t)(bm + ar) * K + k0 + ac);
            int br = ch >> 5, bc = (ch & 31) * 4;
            cp16(sm + BS_BASE + s * BS_STG + br * 136 + bc,
                 B + (size_t)(k0 + br) * N + bn + bc);
        }
        asm volatile("cp.async.commit_group;");
    };

    float acc[2][8][4];
    #pragma unroll
    for (int mf = 0; mf < 2; mf++)
        #pragma unroll
        for (int nf = 0; nf < 8; nf++)
            #pragma unroll
            for (int i = 0; i < 4; i++) acc[mf][nf][i] = 0.0f;

    issue(0, 0);
    issue(1, 1);

    for (int kt = 0; kt < nt; kt++) {
        asm volatile("cp.async.wait_group 1;" ::: "memory");
        __syncthreads();
        const unsigned* As = sm + (kt & 1) * AS_STG;
        const unsigned* Bs = sm + BS_BASE + (kt & 1) * BS_STG;

        #pragma unroll
        for (int ks = 0; ks < 4; ks++) {
            unsigned a[2][4];
            #pragma unroll
            for (int mf = 0; mf < 2; mf++) {
                int r = wm * 32 + mf * 16;
                a[mf][0] = As[(r + g    ) * 36 + ks * 8 + tg];
                a[mf][1] = As[(r + g + 8) * 36 + ks * 8 + tg];
                a[mf][2] = As[(r + g    ) * 36 + ks * 8 + tg + 4];
                a[mf][3] = As[(r + g + 8) * 36 + ks * 8 + tg + 4];
            }
            #pragma unroll
            for (int nf = 0; nf < 8; nf++) {
                unsigned bb[2];
                int c = wn * 64 + nf * 8 + g;
                bb[0] = Bs[(ks * 8 + tg    ) * 136 + c];
                bb[1] = Bs[(ks * 8 + tg + 4) * 136 + c];
                mma8(acc[0][nf], a[0], bb);
                mma8(acc[1][nf], a[1], bb);
            }
        }
        __syncthreads();
        if (kt + 2 < nt) issue(kt + 2, kt & 1);
        else asm volatile("cp.async.commit_group;");  // keep group count in sync
    }

    #pragma unroll
    for (int mf = 0; mf < 2; mf++)
        #pragma unroll
        for (int nf = 0; nf < 8; nf++) {
            int row = bm + wm * 32 + mf * 16 + g;
            int col = bn + wn * 64 + nf * 8 + 2 * tg;
            float c0 = acc[mf][nf][0], c1 = acc[mf][nf][1];
            float c2 = acc[mf][nf][2], c3 = acc[mf][nf][3];
            if (ROPE) {
                if (col < 2 * EMB) {
                    int d = col & 63;  // even dim index within head
                    float freq = exp2f((float)d * -0.2076205059304601f); // 10000^(-d/64)
                    int s0 = row & (SEQ - 1);
                    int s1 = (row + 8) & (SEQ - 1);
                    float sn0, cs0, sn1, cs1;
                    sincosf((float)s0 * freq, &sn0, &cs0);
                    sincosf((float)s1 * freq, &sn1, &cs1);
                    float n0 = c0 * cs0 - c1 * sn0, n1 = c0 * sn0 + c1 * cs0;
                    float n2 = c2 * cs1 - c3 * sn1, n3 = c2 * sn1 + c3 * cs1;
                    c0 = n0; c1 = n1; c2 = n2; c3 = n3;
                }
                c0 = __uint_as_float(f2tf(c0)); c1 = __uint_as_float(f2tf(c1));
                c2 = __uint_as_float(f2tf(c2)); c3 = __uint_as_float(f2tf(c3));
            }
            *(float2*)(C + (size_t)row * N + col)       = make_float2(c0, c1);
            *(float2*)(C + (size_t)(row + 8) * N + col) = make_float2(c2, c3);
        }
}

// ---------------------------------------------------------------------------
// Flash attention (round-6 structure), tf32 mma. Inputs are tf32 bit patterns,
// so no conversion on Q/K/V. Block = 128 threads (4 warps), 64 q-rows x 64 kv.
// Output written as tf32 bits (consumed by the pre-converted out-proj GEMM).
// ---------------------------------------------------------------------------
__global__ __launch_bounds__(128, 3) void attn_mma(
    const float* __restrict__ qkv, float* __restrict__ out)
{
    __shared__ unsigned KP[64][68];
    __shared__ unsigned Vs[64][72];

    const int tid  = threadIdx.x;
    const int lane = tid & 31;
    const int warp = tid >> 5;
    const int g    = lane >> 2;
    const int tg   = lane & 3;
    const int qt   = blockIdx.x;
    const int h    = blockIdx.y;
    const int b    = blockIdx.z;
    const int q0   = qt * 64;
    const int m0   = warp * 16;

    const float* qb = qkv + (size_t)b * SEQ * QKV3 + h * HD;
    const float* kb = qb + EMB;
    const float* vb = qb + 2 * EMB;

    // Q fragments: values are tf32 bits; *0.125f is exact (power of two).
    unsigned qa[8][4];
    #pragma unroll
    for (int ks = 0; ks < 8; ks++) {
        const float* r0p = qb + (size_t)(q0 + m0 + g) * QKV3 + ks * 8 + tg;
        const float* r1p = r0p + (size_t)8 * QKV3;
        qa[ks][0] = __float_as_uint(0.125f * r0p[0]);
        qa[ks][1] = __float_as_uint(0.125f * r1p[0]);
        qa[ks][2] = __float_as_uint(0.125f * r0p[4]);
        qa[ks][3] = __float_as_uint(0.125f * r1p[4]);
    }

    float m_r[2] = {-1e30f, -1e30f};
    float l_r[2] = {0.0f, 0.0f};
    float o[8][4];
    #pragma unroll
    for (int nf = 0; nf < 8; nf++)
        #pragma unroll
        for (int i = 0; i < 4; i++) o[nf][i] = 0.0f;

    for (int kt = 0; kt <= qt; kt++) {
        const int k0 = kt * 64;
        __syncthreads();

        // K,V tiles: raw copies (already tf32 bits)
        for (int idx = tid; idx < 64 * 16; idx += 128) {
            int r = idx >> 4, c4 = (idx & 15) * 4;
            *(uint4*)&KP[r][c4] = *(const uint4*)(kb + (size_t)(k0 + r) * QKV3 + c4);
            *(uint4*)&Vs[r][c4] = *(const uint4*)(vb + (size_t)(k0 + r) * QKV3 + c4);
        }
        __syncthreads();

        // S = (Q/8) @ K^T
        float s[8][4];
        #pragma unroll
        for (int nf = 0; nf < 8; nf++)
            #pragma unroll
            for (int i = 0; i < 4; i++) s[nf][i] = 0.0f;

        #pragma unroll
        for (int ks = 0; ks < 8; ks++) {
            #pragma unroll
            for (int nf = 0; nf < 8; nf++) {
                unsigned bb[2];
                bb[0] = KP[nf * 8 + g][ks * 8 + tg];
                bb[1] = KP[nf * 8 + g][ks * 8 + tg + 4];
                mma8(s[nf], qa[ks], bb);
            }
        }

        if (kt == qt) {   // causal mask, diagonal tile only
            #pragma unroll
            for (int nf = 0; nf < 8; nf++) {
                int col = nf * 8 + 2 * tg;
                int r0 = m0 + g, r1 = r0 + 8;
                if (col     > r0) s[nf][0] = -1e9f;
                if (col + 1 > r0) s[nf][1] = -1e9f;
                if (col     > r1) s[nf][2] = -1e9f;
                if (col + 1 > r1) s[nf][3] = -1e9f;
            }
        }

        // online softmax
        #pragma unroll
        for (int i = 0; i < 2; i++) {
            float mx = -1e30f;
            #pragma unroll
            for (int nf = 0; nf < 8; nf++)
                mx = fmaxf(mx, fmaxf(s[nf][2 * i], s[nf][2 * i + 1]));
            mx = fmaxf(mx, __shfl_xor_sync(0xffffffffu, mx, 1));
            mx = fmaxf(mx, __shfl_xor_sync(0xffffffffu, mx, 2));
            float mn   = fmaxf(m_r[i], mx);
            float corr = __expf(m_r[i] - mn);
            m_r[i] = mn;
            float rs = 0.0f;
            #pragma unroll
            for (int nf = 0; nf < 8; nf++) {
                float p0 = __expf(s[nf][2 * i]     - mn);
                float p1 = __expf(s[nf][2 * i + 1] - mn);
                s[nf][2 * i] = p0; s[nf][2 * i + 1] = p1;
                rs += p0 + p1;
            }
            rs += __shfl_xor_sync(0xffffffffu, rs, 1);
            rs += __shfl_xor_sync(0xffffffffu, rs, 2);
            l_r[i] = l_r[i] * corr + rs;
            #pragma unroll
            for (int nf = 0; nf < 8; nf++) {
                o[nf][2 * i]     *= corr;
                o[nf][2 * i + 1] *= corr;
            }
        }

        __syncthreads();
        // P transposed into KP (tf32 bits)
        #pragma unroll
        for (int nf = 0; nf < 8; nf++) {
            int col = nf * 8 + 2 * tg;
            *(uint2*)&KP[m0 + g    ][col] = make_uint2(f2tf(s[nf][0]), f2tf(s[nf][1]));
            *(uint2*)&KP[m0 + g + 8][col] = make_uint2(f2tf(s[nf][2]), f2tf(s[nf][3]));
        }
        __syncthreads();

        // O += P @ V
        #pragma unroll
        for (int ks = 0; ks < 8; ks++) {
            unsigned pa[4];
            pa[0] = KP[m0 + g    ][ks * 8 + tg];
            pa[1] = KP[m0 + g + 8][ks * 8 + tg];
            pa[2] = KP[m0 + g    ][ks * 8 + tg + 4];
            pa[3] = KP[m0 + g + 8][ks * 8 + tg + 4];
            #pragma unroll
            for (int nf = 0; nf < 8; nf++) {
                unsigned bb[2];
                bb[0] = Vs[ks * 8 + tg    ][nf * 8 + g];
                bb[1] = Vs[ks * 8 + tg + 4][nf * 8 + g];
                mma8(o[nf], pa, bb);
            }
        }
    }

    // epilogue: normalize, store tf32 bits to att buffer [b*s, h*d]
    #pragma unroll
    for (int i = 0; i < 2; i++) {
        float inv = 1.0f / l_r[i];
        int row = q0 + m0 + g + 8 * i;
        float* op = out + ((size_t)b * SEQ + row) * EMB + h * HD;
        #pragma unroll
        for (int nf = 0; nf < 8; nf++) {
            int col = nf * 8 + 2 * tg;
            *(float2*)(op + col) = make_float2(
                __uint_as_float(f2tf(o[nf][2 * i]     * inv)),
                __uint_as_float(f2tf(o[nf][2 * i + 1] * inv)));
        }
    }
}

// ---------------------------------------------------------------------------
extern "C" void kernel_launch(void* const* d_in, const int* in_sizes, int n_in,
                              void* d_out, int out_size)
{
    const float* x    = (const float*)d_in[0];   // [2,2048,1024]
    const float* Wqkv = (const float*)d_in[1];   // [1024,3072]
    const float* Wout = (const float*)d_in[2];   // [1024,1024]
    float* out        = (float*)d_out;           // [2,2048,1024]

    float *qkv = nullptr, *att = nullptr;
    unsigned *xt = nullptr, *wqt = nullptr, *wot = nullptr;
    cudaGetSymbolAddress((void**)&qkv, g_qkv);
    cudaGetSymbolAddress((void**)&att, g_att);
    cudaGetSymbolAddress((void**)&xt,  g_xt);
    cudaGetSymbolAddress((void**)&wqt, g_wqt);
    cudaGetSymbolAddress((void**)&wot, g_wot);

    static bool attr_set = false;
    if (!attr_set) {
        cudaFuncSetAttribute(gemm_tc<1>,
            cudaFuncAttributeMaxDynamicSharedMemorySize, GEMM_SMEM_BYTES);
        cudaFuncSetAttribute(gemm_tc<0>,
            cudaFuncAttributeMaxDynamicSharedMemorySize, GEMM_SMEM_BYTES);
        attr_set = true;
    }

    // 0) pre-convert operands to tf32 bit patterns
    {
        int n4x = MROWS * EMB / 4;     // 1048576
        int n4q = EMB * QKV3 / 4;      // 786432
        int n4o = EMB * EMB / 4;       // 262144
        cvt_tf32_kernel<<<(n4x + 255) / 256, 256>>>((const float4*)x,    (uint4*)xt,  n4x);
        cvt_tf32_kernel<<<(n4q + 255) / 256, 256>>>((const float4*)Wqkv, (uint4*)wqt, n4q);
        cvt_tf32_kernel<<<(n4o + 255) / 256, 256>>>((const float4*)Wout, (uint4*)wot, n4o);
    }
    // 1) QKV projection + fused RoPE (tf32-bit output)
    {
        dim3 grid(QKV3 / 128, MROWS / 128);
        gemm_tc<1><<<grid, 256, GEMM_SMEM_BYTES>>>(xt, wqt, qkv, MROWS, QKV3, EMB);
    }
    // 2) Causal flash attention (tf32-bit in/out)
    {
        dim3 grid(SEQ / 64, NH, BATCH);
        attn_mma<<<grid, 128>>>(qkv, att);
    }
    // 3) Output projection (fp32 output)
    {
        dim3 grid(EMB / 128, MROWS / 128);
        gemm_tc<0><<<grid, 256, GEMM_SMEM_BYTES>>>((const unsigned*)att, wot, out,
                                                   MROWS, EMB, EMB);
    }
}